// round 14
// baseline (speedup 1.0000x reference)
#include <cuda_runtime.h>
#include <cuda_bf16.h>
#include <cstdint>

// ---------------- problem constants ----------------
#define S_    64
#define B_    1024
#define D_    512
#define H_    8
#define DH_   64
#define NL_   4
#define DFF_  2048
#define NT    (S_ * B_)          // 65536 tokens
#define BD    (B_ * D_)          // 524288
#define KBITS 32

// ---------------- scratch (no cudaMalloc allowed) ----------------
__device__ float g_x[NT * D_];                                   // residual (fp32)
__device__ float g_qkv[NT * 3 * D_];                             // qkv (fp32)
__device__ float g_pool[B_ * D_];
__device__ __nv_bfloat16 g_ahi[NT * D_];                         // activation hi
__device__ __nv_bfloat16 g_alo[NT * D_];                         // activation lo
__device__ __nv_bfloat16 g_hhi[(size_t)NT * DFF_];               // mlp hidden hi
__device__ __nv_bfloat16 g_hlo[(size_t)NT * DFF_];               // mlp hidden lo
__device__ __nv_bfloat16 g_whi[DFF_ * D_];                       // weight hi (max 1M)
__device__ __nv_bfloat16 g_wlo[DFF_ * D_];                       // weight lo

// ---------------- helpers ----------------
__device__ __forceinline__ uint32_t smem_u32(const void* p) {
    uint32_t a;
    asm("{ .reg .u64 t; cvta.to.shared.u64 t, %1; cvt.u32.u64 %0, t; }" : "=r"(a) : "l"(p));
    return a;
}
__device__ __forceinline__ uint32_t packbf(float a, float b) {
    __nv_bfloat16 ha = __float2bfloat16(a), hb = __float2bfloat16(b);
    return (uint32_t)__bfloat16_as_ushort(ha) | ((uint32_t)__bfloat16_as_ushort(hb) << 16);
}
__device__ __forceinline__ void split2(float a, float b, uint32_t& hi, uint32_t& lo) {
    __nv_bfloat16 ha = __float2bfloat16(a), hb = __float2bfloat16(b);
    float ra = a - __bfloat162float(ha);
    float rb = b - __bfloat162float(hb);
    hi = (uint32_t)__bfloat16_as_ushort(ha) | ((uint32_t)__bfloat16_as_ushort(hb) << 16);
    lo = packbf(ra, rb);
}

#define CP16(dst, src) \
    asm volatile("cp.async.ca.shared.global [%0], [%1], 16;" :: "r"(dst), "l"(src) : "memory")
#define CPCOMMIT() asm volatile("cp.async.commit_group;" ::: "memory")
#define CPWAIT(n)  asm volatile("cp.async.wait_group %0;" :: "n"(n) : "memory")

__device__ __forceinline__ void ldsm4(uint32_t* r, uint32_t addr) {
    asm volatile("ldmatrix.sync.aligned.m8n8.x4.shared.b16 {%0,%1,%2,%3}, [%4];"
                 : "=r"(r[0]), "=r"(r[1]), "=r"(r[2]), "=r"(r[3]) : "r"(addr));
}
__device__ __forceinline__ void mma16816(float* d, const uint32_t* a, const uint32_t* b) {
    asm volatile("mma.sync.aligned.m16n8k16.row.col.f32.bf16.bf16.f32 "
                 "{%0,%1,%2,%3}, {%4,%5,%6,%7}, {%8,%9}, {%0,%1,%2,%3};"
                 : "+f"(d[0]), "+f"(d[1]), "+f"(d[2]), "+f"(d[3])
                 : "r"(a[0]), "r"(a[1]), "r"(a[2]), "r"(a[3]), "r"(b[0]), "r"(b[1]));
}

__device__ __forceinline__ float qgelu(float t) { return t / (1.0f + __expf(-1.702f * t)); }

// smem: 3 stages x 4 arrays x (128 rows x 128B) = 192KB
#define STG_SZ   65536
#define OFF_ALO  16384
#define OFF_WHI  32768
#define OFF_WLO  49152
#define NSTG     3
#define GEMM_SMEM (NSTG * STG_SZ)

// ---------------- MMA GEMM: C[n,m] = epi(sum_k A[n,k]*W[m,k] + bias[m]) ----------------
// CTA tile: 128 tokens x 128 outputs, KC=64, 8 warps (warp tile 64 tok x 32 out).
// Identical math/layout to the best-measured kernel; pipeline deepened to 3 stages
// (prefetch distance 2) to cover chunk-boundary load latency.
// EPI: 0 = f32 +bias ; 1 = f32 +bias+res ; 2 = QuickGELU -> bf16 hi/lo outputs
template <int EPI>
__global__ __launch_bounds__(256, 1) void mma_gemm(
    const __nv_bfloat16* __restrict__ Ahi, const __nv_bfloat16* __restrict__ Alo,
    const __nv_bfloat16* __restrict__ Whi, const __nv_bfloat16* __restrict__ Wlo,
    const float* __restrict__ bias, const float* __restrict__ res,
    float* __restrict__ C, __nv_bfloat16* __restrict__ Chi, __nv_bfloat16* __restrict__ Clo,
    int M, int K)
{
    extern __shared__ __align__(128) char smem[];
    const uint32_t sb = smem_u32(smem);
    const int tid = threadIdx.x;
    const int lane = tid & 31;
    const int wid = tid >> 5;
    const int m0 = blockIdx.x * 128;
    const int n0 = blockIdx.y * 128;
    const int wm = (wid & 1) * 64;
    const int wn = (wid >> 1) * 32;
    const int NCH = K >> 6;
    const int lcc = tid & 7;

    float acc[4][4][4];
    #pragma unroll
    for (int a = 0; a < 4; a++)
        #pragma unroll
        for (int b = 0; b < 4; b++)
            #pragma unroll
            for (int c = 0; c < 4; c++) acc[a][b][c] = 0.0f;

    // ---- stage loader: A 128 rows, W 128 rows, hi+lo each ----
    auto load_stage = [&](int c, int s) {
        const uint32_t stb = sb + s * STG_SZ;
        #pragma unroll
        for (int j = 0; j < 4; j++) {
            const int r = (j * 256 + tid) >> 3;
            const uint32_t dst = (uint32_t)(r * 128 + ((lcc ^ (r & 7)) << 4));
            const size_t aoff = (size_t)(n0 + r) * K + c * 64 + lcc * 8;
            const size_t woff = (size_t)(m0 + r) * K + c * 64 + lcc * 8;
            CP16(stb + dst,           Ahi + aoff);
            CP16(stb + OFF_ALO + dst, Alo + aoff);
            CP16(stb + OFF_WHI + dst, Whi + woff);
            CP16(stb + OFF_WLO + dst, Wlo + woff);
        }
        CPCOMMIT();
    };

    load_stage(0, 0);
    if (NCH > 1) load_stage(1, 1);

    const int g  = lane >> 3;
    const int lr = lane & 7;
    int s_cur = 0;                 // stage slot of chunk c
    int s_nxt2 = 2;                // stage slot for chunk c+2

    for (int c = 0; c < NCH; c++) {
        if (c + 2 < NCH) { load_stage(c + 2, s_nxt2); CPWAIT(2); }
        else if (c + 1 < NCH) { CPWAIT(1); }
        else { CPWAIT(0); }
        __syncthreads();

        const uint32_t stb = sb + s_cur * STG_SZ;
        #pragma unroll
        for (int ks = 0; ks < 4; ks++) {
            // load ALL fragments for this k16-step first
            uint32_t af[4][4], alf[4][4], bf[2][4], blf[2][4];
            #pragma unroll
            for (int mi = 0; mi < 4; mi++) {
                const int row = wm + mi * 16 + ((g & 1) << 3) + lr;
                const int ch = ks * 2 + (g >> 1);
                const uint32_t ad = stb + row * 128 + ((ch ^ (row & 7)) << 4);
                ldsm4(af[mi], ad);
                ldsm4(alf[mi], ad + OFF_ALO);
            }
            #pragma unroll
            for (int np = 0; np < 2; np++) {
                const int row = wn + np * 16 + ((g >> 1) << 3) + lr;
                const int ch = ks * 2 + (g & 1);
                const uint32_t bd = stb + OFF_WHI + row * 128 + ((ch ^ (row & 7)) << 4);
                ldsm4(bf[np], bd);
                ldsm4(blf[np], bd + 16384);
            }
            // pass 1: Ahi*Whi — 16 independent MMAs
            #pragma unroll
            for (int mi = 0; mi < 4; mi++)
                #pragma unroll
                for (int nt = 0; nt < 4; nt++)
                    mma16816(acc[mi][nt], af[mi], &bf[nt >> 1][(nt & 1) * 2]);
            // pass 2: Alo*Whi
            #pragma unroll
            for (int mi = 0; mi < 4; mi++)
                #pragma unroll
                for (int nt = 0; nt < 4; nt++)
                    mma16816(acc[mi][nt], alf[mi], &bf[nt >> 1][(nt & 1) * 2]);
            // pass 3: Ahi*Wlo
            #pragma unroll
            for (int mi = 0; mi < 4; mi++)
                #pragma unroll
                for (int nt = 0; nt < 4; nt++)
                    mma16816(acc[mi][nt], af[mi], &blf[nt >> 1][(nt & 1) * 2]);
        }
        __syncthreads();
        s_cur  = (s_cur  == NSTG - 1) ? 0 : s_cur + 1;
        s_nxt2 = (s_nxt2 == NSTG - 1) ? 0 : s_nxt2 + 1;
    }

    // ---- epilogue ----
    const int r4 = lane >> 2;
    const int c2 = (lane & 3) * 2;
    #pragma unroll
    for (int mi = 0; mi < 4; mi++) {
        #pragma unroll
        for (int nt = 0; nt < 4; nt++) {
            const int row = n0 + wm + mi * 16 + r4;
            const int col = m0 + wn + nt * 8 + c2;
            const float b0 = bias[col], b1 = bias[col + 1];
            float v0 = acc[mi][nt][0] + b0, v1 = acc[mi][nt][1] + b1;
            float v2 = acc[mi][nt][2] + b0, v3 = acc[mi][nt][3] + b1;
            const size_t o0 = (size_t)row * M + col;
            const size_t o1 = (size_t)(row + 8) * M + col;
            if (EPI == 1) {
                const float2 r0 = *(const float2*)&res[o0];
                const float2 r1 = *(const float2*)&res[o1];
                v0 += r0.x; v1 += r0.y; v2 += r1.x; v3 += r1.y;
            }
            if (EPI == 2) {
                v0 = qgelu(v0); v1 = qgelu(v1); v2 = qgelu(v2); v3 = qgelu(v3);
                uint32_t h0, l0, h1, l1;
                split2(v0, v1, h0, l0);
                split2(v2, v3, h1, l1);
                *(uint32_t*)&Chi[o0] = h0; *(uint32_t*)&Clo[o0] = l0;
                *(uint32_t*)&Chi[o1] = h1; *(uint32_t*)&Clo[o1] = l1;
            } else {
                *(float2*)&C[o0] = make_float2(v0, v1);
                *(float2*)&C[o1] = make_float2(v2, v3);
            }
        }
    }
}

// ---------------- weight convert: fp32 -> bf16 hi/lo ----------------
__global__ void wconv_kernel(const float* __restrict__ w,
                             __nv_bfloat16* __restrict__ hi,
                             __nv_bfloat16* __restrict__ lo) {
    const int i = blockIdx.x * blockDim.x + threadIdx.x;
    const float4 v = *(const float4*)&w[i * 4];
    uint32_t h0, l0, h1, l1;
    split2(v.x, v.y, h0, l0);
    split2(v.z, v.w, h1, l1);
    *(uint2*)&hi[i * 4] = make_uint2(h0, h1);
    *(uint2*)&lo[i * 4] = make_uint2(l0, l1);
}

// ---------------- positional encoding add ----------------
__global__ void pe_add_kernel(const float* __restrict__ xin, float* __restrict__ xout) {
    int idx = blockIdx.x * blockDim.x + threadIdx.x;
    int d = idx & (D_ - 1);
    int s = idx >> 19;
    int j2 = d & ~1;
    float ang = (float)s * expf((float)j2 * (-9.210340371976184f / 512.0f));
    float pe = ((d & 1) ? cosf(ang) : sinf(ang)) * 0.04419417382415922f;
    xout[idx] = xin[idx] + pe;
}

// ---------------- layernorm -> bf16 hi/lo ----------------
__global__ void ln_kernel(const float* __restrict__ x,
                          __nv_bfloat16* __restrict__ yhi, __nv_bfloat16* __restrict__ ylo,
                          const float* __restrict__ g, const float* __restrict__ b) {
    const int row = blockIdx.x;
    const int t = threadIdx.x;
    const size_t base = (size_t)row * D_ + t * 4;
    const float4 v = *(const float4*)&x[base];
    float s = v.x + v.y + v.z + v.w;
    float q = v.x * v.x + v.y * v.y + v.z * v.z + v.w * v.w;
    #pragma unroll
    for (int m = 16; m > 0; m >>= 1) {
        s += __shfl_xor_sync(0xffffffffu, s, m);
        q += __shfl_xor_sync(0xffffffffu, q, m);
    }
    __shared__ float ss[4], qq[4];
    if ((t & 31) == 0) { ss[t >> 5] = s; qq[t >> 5] = q; }
    __syncthreads();
    s = ss[0] + ss[1] + ss[2] + ss[3];
    q = qq[0] + qq[1] + qq[2] + qq[3];
    const float mean = s * (1.0f / 512.0f);
    const float var  = q * (1.0f / 512.0f) - mean * mean;
    const float rstd = rsqrtf(var + 1e-5f);
    const float4 gg = *(const float4*)&g[t * 4];
    const float4 bb = *(const float4*)&b[t * 4];
    const float o0 = (v.x - mean) * rstd * gg.x + bb.x;
    const float o1 = (v.y - mean) * rstd * gg.y + bb.y;
    const float o2 = (v.z - mean) * rstd * gg.z + bb.z;
    const float o3 = (v.w - mean) * rstd * gg.w + bb.w;
    uint32_t h0, l0, h1, l1;
    split2(o0, o1, h0, l0);
    split2(o2, o3, h1, l1);
    *(uint2*)&yhi[base] = make_uint2(h0, h1);
    *(uint2*)&ylo[base] = make_uint2(l0, l1);
}

// ---------------- attention: one CTA per (batch, head); bf16 hi/lo output ----------------
__global__ __launch_bounds__(256) void attn_kernel(const float* __restrict__ qkv,
                                                   __nv_bfloat16* __restrict__ ohi,
                                                   __nv_bfloat16* __restrict__ olo) {
    __shared__ __align__(16) float qs[64 * 64];
    __shared__ __align__(16) float kst[64 * 64];
    __shared__ __align__(16) float vs[64 * 64];

    const int b = blockIdx.x;
    const int h = blockIdx.y;
    const int tid = threadIdx.x;
    const float* base = qkv + (size_t)b * (3 * D_) + h * DH_;

    #pragma unroll
    for (int it = 0; it < 4; it++) {
        const int idx = tid + it * 256;
        const int s = idx >> 4;
        const int f = idx & 15;
        const size_t g = (size_t)s * (B_ * 3 * D_) + f * 4;
        const float4 qv = *(const float4*)(base + g);
        const float4 kv = *(const float4*)(base + 512 + g);
        const float4 vv = *(const float4*)(base + 1024 + g);
        *(float4*)&qs[s * 64 + f * 4] = qv;
        kst[(f * 4 + 0) * 64 + s] = kv.x;
        kst[(f * 4 + 1) * 64 + s] = kv.y;
        kst[(f * 4 + 2) * 64 + s] = kv.z;
        kst[(f * 4 + 3) * 64 + s] = kv.w;
        *(float4*)&vs[s * 64 + f * 4] = vv;
    }
    __syncthreads();

    const int tx = tid & 15;
    const int ty = tid >> 4;

    float sc[4][4] = {};
    for (int d0 = 0; d0 < 64; d0 += 4) {
        const float4 k0 = *(const float4*)&kst[(d0 + 0) * 64 + tx * 4];
        const float4 k1 = *(const float4*)&kst[(d0 + 1) * 64 + tx * 4];
        const float4 k2 = *(const float4*)&kst[(d0 + 2) * 64 + tx * 4];
        const float4 k3 = *(const float4*)&kst[(d0 + 3) * 64 + tx * 4];
        #pragma unroll
        for (int i = 0; i < 4; i++) {
            const float4 q = *(const float4*)&qs[(ty * 4 + i) * 64 + d0];
            sc[i][0] += q.x * k0.x + q.y * k1.x + q.z * k2.x + q.w * k3.x;
            sc[i][1] += q.x * k0.y + q.y * k1.y + q.z * k2.y + q.w * k3.y;
            sc[i][2] += q.x * k0.z + q.y * k1.z + q.z * k2.z + q.w * k3.z;
            sc[i][3] += q.x * k0.w + q.y * k1.w + q.z * k2.w + q.w * k3.w;
        }
    }

    float p[4][4];
    #pragma unroll
    for (int i = 0; i < 4; i++) {
        #pragma unroll
        for (int j = 0; j < 4; j++) sc[i][j] *= 0.125f;
        float m = fmaxf(fmaxf(sc[i][0], sc[i][1]), fmaxf(sc[i][2], sc[i][3]));
        #pragma unroll
        for (int msk = 1; msk < 16; msk <<= 1) m = fmaxf(m, __shfl_xor_sync(0xffffffffu, m, msk));
        float s = 0.0f;
        #pragma unroll
        for (int j = 0; j < 4; j++) { p[i][j] = __expf(sc[i][j] - m); s += p[i][j]; }
        #pragma unroll
        for (int msk = 1; msk < 16; msk <<= 1) s += __shfl_xor_sync(0xffffffffu, s, msk);
        const float inv = 1.0f / s;
        #pragma unroll
        for (int j = 0; j < 4; j++) p[i][j] *= inv;
    }

    __syncthreads();
    #pragma unroll
    for (int i = 0; i < 4; i++)
        #pragma unroll
        for (int j = 0; j < 4; j++)
            qs[(ty * 4 + i) * 64 + tx * 4 + j] = p[i][j];
    __syncthreads();

    float oc[4][4] = {};
    #pragma unroll 4
    for (int t = 0; t < 64; t++) {
        const float4 vv = *(const float4*)&vs[t * 64 + tx * 4];
        #pragma unroll
        for (int i = 0; i < 4; i++) {
            const float pp = qs[(ty * 4 + i) * 64 + t];
            oc[i][0] += pp * vv.x; oc[i][1] += pp * vv.y;
            oc[i][2] += pp * vv.z; oc[i][3] += pp * vv.w;
        }
    }
    #pragma unroll
    for (int i = 0; i < 4; i++) {
        const int s = ty * 4 + i;
        const size_t off = (size_t)(s * B_ + b) * D_ + h * DH_ + tx * 4;
        uint32_t h0, l0, h1, l1;
        split2(oc[i][0], oc[i][1], h0, l0);
        split2(oc[i][2], oc[i][3], h1, l1);
        *(uint2*)&ohi[off] = make_uint2(h0, h1);
        *(uint2*)&olo[off] = make_uint2(l0, l1);
    }
}

// ---------------- mean over S ----------------
__global__ void pool_kernel(const float* __restrict__ x, float* __restrict__ pooled) {
    const int idx = blockIdx.x * blockDim.x + threadIdx.x;
    float s = 0.0f;
    #pragma unroll
    for (int t = 0; t < S_; t++) s += x[(size_t)t * BD + idx];
    pooled[idx] = s * (1.0f / 64.0f);
}

// ---------------- hashing head ----------------
__global__ void hash_kernel(const float* __restrict__ pooled, const float* __restrict__ hw,
                            const float* __restrict__ hb, float* __restrict__ out) {
    const int b = blockIdx.x;
    const int t = threadIdx.x;
    __shared__ float row[512];
    __shared__ float part[128];
    *(float4*)&row[t * 4] = *(const float4*)&pooled[(size_t)b * D_ + t * 4];
    __syncthreads();
    const int k = t & 31;
    const int pi = t >> 5;
    const float* w = hw + (size_t)k * D_ + pi * 128;
    const float* r = row + pi * 128;
    float s = 0.0f;
    #pragma unroll 8
    for (int d = 0; d < 128; d++) s += r[d] * w[d];
    part[t] = s;
    __syncthreads();
    if (t < 32) {
        const float v = part[t] + part[t + 32] + part[t + 64] + part[t + 96] + hb[t];
        out[(size_t)b * KBITS + t] = tanhf(v);
    }
}

// ---------------- orchestration ----------------
extern "C" void kernel_launch(void* const* d_in, const int* in_sizes, int n_in,
                              void* d_out, int out_size) {
    const float* x_in  = (const float*)d_in[0];
    const float* ln1_g = (const float*)d_in[1];
    const float* ln1_b = (const float*)d_in[2];
    const float* qkv_w = (const float*)d_in[3];
    const float* qkv_b = (const float*)d_in[4];
    const float* out_w = (const float*)d_in[5];
    const float* out_b = (const float*)d_in[6];
    const float* ln2_g = (const float*)d_in[7];
    const float* ln2_b = (const float*)d_in[8];
    const float* w1    = (const float*)d_in[9];
    const float* b1    = (const float*)d_in[10];
    const float* w2    = (const float*)d_in[11];
    const float* b2    = (const float*)d_in[12];
    const float* hw    = (const float*)d_in[13];
    const float* hb    = (const float*)d_in[14];
    float* out = (float*)d_out;

    float *gx, *gqkv, *gpool;
    __nv_bfloat16 *ahi, *alo, *hhi, *hlo, *whi, *wlo;
    cudaGetSymbolAddress((void**)&gx,    g_x);
    cudaGetSymbolAddress((void**)&gqkv,  g_qkv);
    cudaGetSymbolAddress((void**)&gpool, g_pool);
    cudaGetSymbolAddress((void**)&ahi,   g_ahi);
    cudaGetSymbolAddress((void**)&alo,   g_alo);
    cudaGetSymbolAddress((void**)&hhi,   g_hhi);
    cudaGetSymbolAddress((void**)&hlo,   g_hlo);
    cudaGetSymbolAddress((void**)&whi,   g_whi);
    cudaGetSymbolAddress((void**)&wlo,   g_wlo);

    cudaFuncSetAttribute(mma_gemm<0>, cudaFuncAttributeMaxDynamicSharedMemorySize, GEMM_SMEM);
    cudaFuncSetAttribute(mma_gemm<1>, cudaFuncAttributeMaxDynamicSharedMemorySize, GEMM_SMEM);
    cudaFuncSetAttribute(mma_gemm<2>, cudaFuncAttributeMaxDynamicSharedMemorySize, GEMM_SMEM);

    pe_add_kernel<<<(NT * D_) / 256, 256>>>(x_in, gx);

    for (int i = 0; i < NL_; i++) {
        // --- attention block ---
        ln_kernel<<<NT, 128>>>(gx, ahi, alo, ln1_g + i * D_, ln1_b + i * D_);
        wconv_kernel<<<(3 * D_ * D_) / 1024, 256>>>(qkv_w + (size_t)i * 3 * D_ * D_, whi, wlo);
        mma_gemm<0><<<dim3(12, 512), 256, GEMM_SMEM>>>(
            ahi, alo, whi, wlo, qkv_b + (size_t)i * 3 * D_, nullptr,
            gqkv, nullptr, nullptr, 3 * D_, D_);
        attn_kernel<<<dim3(B_, H_), 256>>>(gqkv, ahi, alo);
        wconv_kernel<<<(D_ * D_) / 1024, 256>>>(out_w + (size_t)i * D_ * D_, whi, wlo);
        mma_gemm<1><<<dim3(4, 512), 256, GEMM_SMEM>>>(
            ahi, alo, whi, wlo, out_b + (size_t)i * D_, gx,
            gx, nullptr, nullptr, D_, D_);
        // --- MLP block ---
        ln_kernel<<<NT, 128>>>(gx, ahi, alo, ln2_g + i * D_, ln2_b + i * D_);
        wconv_kernel<<<(DFF_ * D_) / 1024, 256>>>(w1 + (size_t)i * DFF_ * D_, whi, wlo);
        mma_gemm<2><<<dim3(16, 512), 256, GEMM_SMEM>>>(
            ahi, alo, whi, wlo, b1 + (size_t)i * DFF_, nullptr,
            nullptr, hhi, hlo, DFF_, D_);
        wconv_kernel<<<(D_ * DFF_) / 1024, 256>>>(w2 + (size_t)i * D_ * DFF_, whi, wlo);
        mma_gemm<1><<<dim3(4, 512), 256, GEMM_SMEM>>>(
            hhi, hlo, whi, wlo, b2 + (size_t)i * D_, gx,
            gx, nullptr, nullptr, D_, DFF_);
    }

    pool_kernel<<<(B_ * D_) / 256, 256>>>(gx, gpool);
    hash_kernel<<<B_, 128>>>(gpool, hw, hb, out);
}

// round 15
// speedup vs baseline: 1.6831x; 1.6831x over previous
#include <cuda_runtime.h>
#include <cuda_bf16.h>
#include <cstdint>

// ---------------- problem constants ----------------
#define S_    64
#define B_    1024
#define D_    512
#define H_    8
#define DH_   64
#define NL_   4
#define DFF_  2048
#define NT    (S_ * B_)          // 65536 tokens
#define BD    (B_ * D_)          // 524288
#define KBITS 32

// ---------------- scratch (no cudaMalloc allowed) ----------------
__device__ float g_x[NT * D_];                                   // residual (fp32)
__device__ float g_qkv[NT * 3 * D_];                             // qkv (fp32)
__device__ float g_pool[B_ * D_];
__device__ __nv_bfloat16 g_ahi[NT * D_];                         // activation hi
__device__ __nv_bfloat16 g_alo[NT * D_];                         // activation lo
__device__ __nv_bfloat16 g_hhi[(size_t)NT * DFF_];               // mlp hidden hi
__device__ __nv_bfloat16 g_hlo[(size_t)NT * DFF_];               // mlp hidden lo
__device__ __nv_bfloat16 g_whi[DFF_ * D_];                       // weight hi (max 1M)
__device__ __nv_bfloat16 g_wlo[DFF_ * D_];                       // weight lo

// ---------------- helpers ----------------
__device__ __forceinline__ uint32_t smem_u32(const void* p) {
    uint32_t a;
    asm("{ .reg .u64 t; cvta.to.shared.u64 t, %1; cvt.u32.u64 %0, t; }" : "=r"(a) : "l"(p));
    return a;
}
__device__ __forceinline__ uint32_t packbf(float a, float b) {
    __nv_bfloat16 ha = __float2bfloat16(a), hb = __float2bfloat16(b);
    return (uint32_t)__bfloat16_as_ushort(ha) | ((uint32_t)__bfloat16_as_ushort(hb) << 16);
}
__device__ __forceinline__ void split2(float a, float b, uint32_t& hi, uint32_t& lo) {
    __nv_bfloat16 ha = __float2bfloat16(a), hb = __float2bfloat16(b);
    float ra = a - __bfloat162float(ha);
    float rb = b - __bfloat162float(hb);
    hi = (uint32_t)__bfloat16_as_ushort(ha) | ((uint32_t)__bfloat16_as_ushort(hb) << 16);
    lo = packbf(ra, rb);
}

#define CP16(dst, src) \
    asm volatile("cp.async.ca.shared.global [%0], [%1], 16;" :: "r"(dst), "l"(src) : "memory")
#define CPCOMMIT() asm volatile("cp.async.commit_group;" ::: "memory")
#define CPWAIT(n)  asm volatile("cp.async.wait_group %0;" :: "n"(n) : "memory")

__device__ __forceinline__ void ldsm4(uint32_t* r, uint32_t addr) {
    asm volatile("ldmatrix.sync.aligned.m8n8.x4.shared.b16 {%0,%1,%2,%3}, [%4];"
                 : "=r"(r[0]), "=r"(r[1]), "=r"(r[2]), "=r"(r[3]) : "r"(addr));
}
__device__ __forceinline__ void mma16816(float* d, const uint32_t* a, const uint32_t* b) {
    asm volatile("mma.sync.aligned.m16n8k16.row.col.f32.bf16.bf16.f32 "
                 "{%0,%1,%2,%3}, {%4,%5,%6,%7}, {%8,%9}, {%0,%1,%2,%3};"
                 : "+f"(d[0]), "+f"(d[1]), "+f"(d[2]), "+f"(d[3])
                 : "r"(a[0]), "r"(a[1]), "r"(a[2]), "r"(a[3]), "r"(b[0]), "r"(b[1]));
}

__device__ __forceinline__ float qgelu(float t) { return t / (1.0f + __expf(-1.702f * t)); }

// smem: 2 stages x 4 arrays x (128 rows x 128B) = 128KB
#define STG_SZ   65536
#define OFF_ALO  16384
#define OFF_WHI  32768
#define OFF_WLO  49152
#define GEMM_SMEM (2 * STG_SZ)

// ---------------- MMA GEMM (exact best-measured R3 kernel) ----------------
// CTA tile: 128 tokens x 128 outputs, KC=64, 8 warps (warp tile 64 tok x 32 out).
// EPI: 0 = f32 +bias ; 1 = f32 +bias+res ; 2 = QuickGELU -> bf16 hi/lo outputs
template <int EPI>
__global__ __launch_bounds__(256, 1) void mma_gemm(
    const __nv_bfloat16* __restrict__ Ahi, const __nv_bfloat16* __restrict__ Alo,
    const __nv_bfloat16* __restrict__ Whi, const __nv_bfloat16* __restrict__ Wlo,
    const float* __restrict__ bias, const float* __restrict__ res,
    float* __restrict__ C, __nv_bfloat16* __restrict__ Chi, __nv_bfloat16* __restrict__ Clo,
    int M, int K)
{
    extern __shared__ __align__(128) char smem[];
    const uint32_t sb = smem_u32(smem);
    const int tid = threadIdx.x;
    const int lane = tid & 31;
    const int wid = tid >> 5;
    const int m0 = blockIdx.x * 128;
    const int n0 = blockIdx.y * 128;
    const int wm = (wid & 1) * 64;
    const int wn = (wid >> 1) * 32;
    const int NCH = K >> 6;
    const int lcc = tid & 7;

    float acc[4][4][4];
    #pragma unroll
    for (int a = 0; a < 4; a++)
        #pragma unroll
        for (int b = 0; b < 4; b++)
            #pragma unroll
            for (int c = 0; c < 4; c++) acc[a][b][c] = 0.0f;

    auto load_stage = [&](int c, int s) {
        const uint32_t stb = sb + s * STG_SZ;
        #pragma unroll
        for (int j = 0; j < 4; j++) {
            const int r = (j * 256 + tid) >> 3;
            const uint32_t dst = (uint32_t)(r * 128 + ((lcc ^ (r & 7)) << 4));
            const size_t aoff = (size_t)(n0 + r) * K + c * 64 + lcc * 8;
            const size_t woff = (size_t)(m0 + r) * K + c * 64 + lcc * 8;
            CP16(stb + dst,           Ahi + aoff);
            CP16(stb + OFF_ALO + dst, Alo + aoff);
            CP16(stb + OFF_WHI + dst, Whi + woff);
            CP16(stb + OFF_WLO + dst, Wlo + woff);
        }
        CPCOMMIT();
    };

    load_stage(0, 0);

    const int g  = lane >> 3;
    const int lr = lane & 7;

    for (int c = 0; c < NCH; c++) {
        if (c + 1 < NCH) { load_stage(c + 1, (c + 1) & 1); CPWAIT(1); }
        else             { CPWAIT(0); }
        __syncthreads();

        const uint32_t stb = sb + (c & 1) * STG_SZ;
        #pragma unroll
        for (int ks = 0; ks < 4; ks++) {
            uint32_t af[4][4], alf[4][4], bf[2][4], blf[2][4];
            #pragma unroll
            for (int mi = 0; mi < 4; mi++) {
                const int row = wm + mi * 16 + ((g & 1) << 3) + lr;
                const int ch = ks * 2 + (g >> 1);
                const uint32_t ad = stb + row * 128 + ((ch ^ (row & 7)) << 4);
                ldsm4(af[mi], ad);
                ldsm4(alf[mi], ad + OFF_ALO);
            }
            #pragma unroll
            for (int np = 0; np < 2; np++) {
                const int row = wn + np * 16 + ((g >> 1) << 3) + lr;
                const int ch = ks * 2 + (g & 1);
                const uint32_t bd = stb + OFF_WHI + row * 128 + ((ch ^ (row & 7)) << 4);
                ldsm4(bf[np], bd);
                ldsm4(blf[np], bd + 16384);
            }
            #pragma unroll
            for (int mi = 0; mi < 4; mi++)
                #pragma unroll
                for (int nt = 0; nt < 4; nt++)
                    mma16816(acc[mi][nt], af[mi], &bf[nt >> 1][(nt & 1) * 2]);
            #pragma unroll
            for (int mi = 0; mi < 4; mi++)
                #pragma unroll
                for (int nt = 0; nt < 4; nt++)
                    mma16816(acc[mi][nt], alf[mi], &bf[nt >> 1][(nt & 1) * 2]);
            #pragma unroll
            for (int mi = 0; mi < 4; mi++)
                #pragma unroll
                for (int nt = 0; nt < 4; nt++)
                    mma16816(acc[mi][nt], af[mi], &blf[nt >> 1][(nt & 1) * 2]);
        }
        __syncthreads();
    }

    const int r4 = lane >> 2;
    const int c2 = (lane & 3) * 2;
    #pragma unroll
    for (int mi = 0; mi < 4; mi++) {
        #pragma unroll
        for (int nt = 0; nt < 4; nt++) {
            const int row = n0 + wm + mi * 16 + r4;
            const int col = m0 + wn + nt * 8 + c2;
            const float b0 = bias[col], b1 = bias[col + 1];
            float v0 = acc[mi][nt][0] + b0, v1 = acc[mi][nt][1] + b1;
            float v2 = acc[mi][nt][2] + b0, v3 = acc[mi][nt][3] + b1;
            const size_t o0 = (size_t)row * M + col;
            const size_t o1 = (size_t)(row + 8) * M + col;
            if (EPI == 1) {
                const float2 r0 = *(const float2*)&res[o0];
                const float2 r1 = *(const float2*)&res[o1];
                v0 += r0.x; v1 += r0.y; v2 += r1.x; v3 += r1.y;
            }
            if (EPI == 2) {
                v0 = qgelu(v0); v1 = qgelu(v1); v2 = qgelu(v2); v3 = qgelu(v3);
                uint32_t h0, l0, h1, l1;
                split2(v0, v1, h0, l0);
                split2(v2, v3, h1, l1);
                *(uint32_t*)&Chi[o0] = h0; *(uint32_t*)&Clo[o0] = l0;
                *(uint32_t*)&Chi[o1] = h1; *(uint32_t*)&Clo[o1] = l1;
            } else {
                *(float2*)&C[o0] = make_float2(v0, v1);
                *(float2*)&C[o1] = make_float2(v2, v3);
            }
        }
    }
}

// ---------------- weight convert: fp32 -> bf16 hi/lo ----------------
__global__ void wconv_kernel(const float* __restrict__ w,
                             __nv_bfloat16* __restrict__ hi,
                             __nv_bfloat16* __restrict__ lo) {
    const int i = blockIdx.x * blockDim.x + threadIdx.x;
    const float4 v = *(const float4*)&w[i * 4];
    uint32_t h0, l0, h1, l1;
    split2(v.x, v.y, h0, l0);
    split2(v.z, v.w, h1, l1);
    *(uint2*)&hi[i * 4] = make_uint2(h0, h1);
    *(uint2*)&lo[i * 4] = make_uint2(l0, l1);
}

// ---------------- positional encoding add ----------------
__global__ void pe_add_kernel(const float* __restrict__ xin, float* __restrict__ xout) {
    int idx = blockIdx.x * blockDim.x + threadIdx.x;
    int d = idx & (D_ - 1);
    int s = idx >> 19;
    int j2 = d & ~1;
    float ang = (float)s * expf((float)j2 * (-9.210340371976184f / 512.0f));
    float pe = ((d & 1) ? cosf(ang) : sinf(ang)) * 0.04419417382415922f;
    xout[idx] = xin[idx] + pe;
}

// ---------------- layernorm -> bf16 hi/lo ----------------
__global__ void ln_kernel(const float* __restrict__ x,
                          __nv_bfloat16* __restrict__ yhi, __nv_bfloat16* __restrict__ ylo,
                          const float* __restrict__ g, const float* __restrict__ b) {
    const int row = blockIdx.x;
    const int t = threadIdx.x;
    const size_t base = (size_t)row * D_ + t * 4;
    const float4 v = *(const float4*)&x[base];
    float s = v.x + v.y + v.z + v.w;
    float q = v.x * v.x + v.y * v.y + v.z * v.z + v.w * v.w;
    #pragma unroll
    for (int m = 16; m > 0; m >>= 1) {
        s += __shfl_xor_sync(0xffffffffu, s, m);
        q += __shfl_xor_sync(0xffffffffu, q, m);
    }
    __shared__ float ss[4], qq[4];
    if ((t & 31) == 0) { ss[t >> 5] = s; qq[t >> 5] = q; }
    __syncthreads();
    s = ss[0] + ss[1] + ss[2] + ss[3];
    q = qq[0] + qq[1] + qq[2] + qq[3];
    const float mean = s * (1.0f / 512.0f);
    const float var  = q * (1.0f / 512.0f) - mean * mean;
    const float rstd = rsqrtf(var + 1e-5f);
    const float4 gg = *(const float4*)&g[t * 4];
    const float4 bb = *(const float4*)&b[t * 4];
    const float o0 = (v.x - mean) * rstd * gg.x + bb.x;
    const float o1 = (v.y - mean) * rstd * gg.y + bb.y;
    const float o2 = (v.z - mean) * rstd * gg.z + bb.z;
    const float o3 = (v.w - mean) * rstd * gg.w + bb.w;
    uint32_t h0, l0, h1, l1;
    split2(o0, o1, h0, l0);
    split2(o2, o3, h1, l1);
    *(uint2*)&yhi[base] = make_uint2(h0, h1);
    *(uint2*)&ylo[base] = make_uint2(l0, l1);
}

// ---------------- attention: one CTA per (batch, head); bf16 hi/lo output ----------------
// kst uses an XOR swizzle: element (d, t) lives at kst[d*64 + (t ^ (4*(d>>2)))].
// Transpose stores drop from 16-way to 2-way conflicts; score-loop reads stay
// aligned float4 (d0 steps by 4 so the XOR constant is uniform within a step).
__global__ __launch_bounds__(256) void attn_kernel(const float* __restrict__ qkv,
                                                   __nv_bfloat16* __restrict__ ohi,
                                                   __nv_bfloat16* __restrict__ olo) {
    __shared__ __align__(16) float qs[64 * 64];
    __shared__ __align__(16) float kst[64 * 64];
    __shared__ __align__(16) float vs[64 * 64];

    const int b = blockIdx.x;
    const int h = blockIdx.y;
    const int tid = threadIdx.x;
    const float* base = qkv + (size_t)b * (3 * D_) + h * DH_;

    #pragma unroll
    for (int it = 0; it < 4; it++) {
        const int idx = tid + it * 256;
        const int s = idx >> 4;
        const int f = idx & 15;              // d = 4f..4f+3
        const size_t g = (size_t)s * (B_ * 3 * D_) + f * 4;
        const float4 qv = *(const float4*)(base + g);
        const float4 kv = *(const float4*)(base + 512 + g);
        const float4 vv = *(const float4*)(base + 1024 + g);
        *(float4*)&qs[s * 64 + f * 4] = qv;
        const int swc = s ^ (f * 4);         // swizzled column (same for all 4 rows)
        kst[(f * 4 + 0) * 64 + swc] = kv.x;
        kst[(f * 4 + 1) * 64 + swc] = kv.y;
        kst[(f * 4 + 2) * 64 + swc] = kv.z;
        kst[(f * 4 + 3) * 64 + swc] = kv.w;
        *(float4*)&vs[s * 64 + f * 4] = vv;
    }
    __syncthreads();

    const int tx = tid & 15;
    const int ty = tid >> 4;

    float sc[4][4] = {};
    #pragma unroll 4
    for (int d0 = 0; d0 < 64; d0 += 4) {
        const int txx = (tx ^ (d0 >> 2)) * 4;    // de-swizzled float4 position
        const float4 k0 = *(const float4*)&kst[(d0 + 0) * 64 + txx];
        const float4 k1 = *(const float4*)&kst[(d0 + 1) * 64 + txx];
        const float4 k2 = *(const float4*)&kst[(d0 + 2) * 64 + txx];
        const float4 k3 = *(const float4*)&kst[(d0 + 3) * 64 + txx];
        #pragma unroll
        for (int i = 0; i < 4; i++) {
            const float4 q = *(const float4*)&qs[(ty * 4 + i) * 64 + d0];
            sc[i][0] += q.x * k0.x + q.y * k1.x + q.z * k2.x + q.w * k3.x;
            sc[i][1] += q.x * k0.y + q.y * k1.y + q.z * k2.y + q.w * k3.y;
            sc[i][2] += q.x * k0.z + q.y * k1.z + q.z * k2.z + q.w * k3.z;
            sc[i][3] += q.x * k0.w + q.y * k1.w + q.z * k2.w + q.w * k3.w;
        }
    }
    // undo the column permutation: lane tx computed t-columns 4*(tx^(d0>>2))..+3,
    // but the XOR varies with d0 — wait, scores accumulate over d for FIXED t.
    // With txx varying by d0 the t-columns differ per d0 step: must keep t fixed.
    // Correction applied: read the SAME t for all d0 by de-swizzling per step.
    // (kst[(d0+j)*64 + ((tx*4) ^ (4*(d0>>2)))] == k[d0+j][ derived t ].)
    // The float4 at position 4*(tx^(d0>>2)) holds t = 4*(tx^(d0>>2))..+3 after
    // inverting: col c holds t = c ^ (4*(d0>>2)); choosing c = 4*(tx^(d0>>2))
    // yields t = 4*tx..4*tx+3 exactly. So sc[i][j] is t = 4*tx+j for all steps. OK.

    float p[4][4];
    #pragma unroll
    for (int i = 0; i < 4; i++) {
        #pragma unroll
        for (int j = 0; j < 4; j++) sc[i][j] *= 0.125f;
        float m = fmaxf(fmaxf(sc[i][0], sc[i][1]), fmaxf(sc[i][2], sc[i][3]));
        #pragma unroll
        for (int msk = 1; msk < 16; msk <<= 1) m = fmaxf(m, __shfl_xor_sync(0xffffffffu, m, msk));
        float s = 0.0f;
        #pragma unroll
        for (int j = 0; j < 4; j++) { p[i][j] = __expf(sc[i][j] - m); s += p[i][j]; }
        #pragma unroll
        for (int msk = 1; msk < 16; msk <<= 1) s += __shfl_xor_sync(0xffffffffu, s, msk);
        const float inv = 1.0f / s;
        #pragma unroll
        for (int j = 0; j < 4; j++) p[i][j] *= inv;
    }

    __syncthreads();
    #pragma unroll
    for (int i = 0; i < 4; i++)
        *(float4*)&qs[(ty * 4 + i) * 64 + tx * 4] =
            make_float4(p[i][0], p[i][1], p[i][2], p[i][3]);
    __syncthreads();

    float oc[4][4] = {};
    #pragma unroll 4
    for (int t = 0; t < 64; t++) {
        const float4 vv = *(const float4*)&vs[t * 64 + tx * 4];
        #pragma unroll
        for (int i = 0; i < 4; i++) {
            const float pp = qs[(ty * 4 + i) * 64 + t];
            oc[i][0] += pp * vv.x; oc[i][1] += pp * vv.y;
            oc[i][2] += pp * vv.z; oc[i][3] += pp * vv.w;
        }
    }
    #pragma unroll
    for (int i = 0; i < 4; i++) {
        const int s = ty * 4 + i;
        const size_t off = (size_t)(s * B_ + b) * D_ + h * DH_ + tx * 4;
        uint32_t h0, l0, h1, l1;
        split2(oc[i][0], oc[i][1], h0, l0);
        split2(oc[i][2], oc[i][3], h1, l1);
        *(uint2*)&ohi[off] = make_uint2(h0, h1);
        *(uint2*)&olo[off] = make_uint2(l0, l1);
    }
}

// ---------------- mean over S ----------------
__global__ void pool_kernel(const float* __restrict__ x, float* __restrict__ pooled) {
    const int idx = blockIdx.x * blockDim.x + threadIdx.x;
    float s = 0.0f;
    #pragma unroll
    for (int t = 0; t < S_; t++) s += x[(size_t)t * BD + idx];
    pooled[idx] = s * (1.0f / 64.0f);
}

// ---------------- hashing head ----------------
__global__ void hash_kernel(const float* __restrict__ pooled, const float* __restrict__ hw,
                            const float* __restrict__ hb, float* __restrict__ out) {
    const int b = blockIdx.x;
    const int t = threadIdx.x;
    __shared__ float row[512];
    __shared__ float part[128];
    *(float4*)&row[t * 4] = *(const float4*)&pooled[(size_t)b * D_ + t * 4];
    __syncthreads();
    const int k = t & 31;
    const int pi = t >> 5;
    const float* w = hw + (size_t)k * D_ + pi * 128;
    const float* r = row + pi * 128;
    float s = 0.0f;
    #pragma unroll 8
    for (int d = 0; d < 128; d++) s += r[d] * w[d];
    part[t] = s;
    __syncthreads();
    if (t < 32) {
        const float v = part[t] + part[t + 32] + part[t + 64] + part[t + 96] + hb[t];
        out[(size_t)b * KBITS + t] = tanhf(v);
    }
}

// ---------------- orchestration ----------------
extern "C" void kernel_launch(void* const* d_in, const int* in_sizes, int n_in,
                              void* d_out, int out_size) {
    const float* x_in  = (const float*)d_in[0];
    const float* ln1_g = (const float*)d_in[1];
    const float* ln1_b = (const float*)d_in[2];
    const float* qkv_w = (const float*)d_in[3];
    const float* qkv_b = (const float*)d_in[4];
    const float* out_w = (const float*)d_in[5];
    const float* out_b = (const float*)d_in[6];
    const float* ln2_g = (const float*)d_in[7];
    const float* ln2_b = (const float*)d_in[8];
    const float* w1    = (const float*)d_in[9];
    const float* b1    = (const float*)d_in[10];
    const float* w2    = (const float*)d_in[11];
    const float* b2    = (const float*)d_in[12];
    const float* hw    = (const float*)d_in[13];
    const float* hb    = (const float*)d_in[14];
    float* out = (float*)d_out;

    float *gx, *gqkv, *gpool;
    __nv_bfloat16 *ahi, *alo, *hhi, *hlo, *whi, *wlo;
    cudaGetSymbolAddress((void**)&gx,    g_x);
    cudaGetSymbolAddress((void**)&gqkv,  g_qkv);
    cudaGetSymbolAddress((void**)&gpool, g_pool);
    cudaGetSymbolAddress((void**)&ahi,   g_ahi);
    cudaGetSymbolAddress((void**)&alo,   g_alo);
    cudaGetSymbolAddress((void**)&hhi,   g_hhi);
    cudaGetSymbolAddress((void**)&hlo,   g_hlo);
    cudaGetSymbolAddress((void**)&whi,   g_whi);
    cudaGetSymbolAddress((void**)&wlo,   g_wlo);

    cudaFuncSetAttribute(mma_gemm<0>, cudaFuncAttributeMaxDynamicSharedMemorySize, GEMM_SMEM);
    cudaFuncSetAttribute(mma_gemm<1>, cudaFuncAttributeMaxDynamicSharedMemorySize, GEMM_SMEM);
    cudaFuncSetAttribute(mma_gemm<2>, cudaFuncAttributeMaxDynamicSharedMemorySize, GEMM_SMEM);

    pe_add_kernel<<<(NT * D_) / 256, 256>>>(x_in, gx);

    for (int i = 0; i < NL_; i++) {
        // --- attention block ---
        ln_kernel<<<NT, 128>>>(gx, ahi, alo, ln1_g + i * D_, ln1_b + i * D_);
        wconv_kernel<<<(3 * D_ * D_) / 1024, 256>>>(qkv_w + (size_t)i * 3 * D_ * D_, whi, wlo);
        mma_gemm<0><<<dim3(12, 512), 256, GEMM_SMEM>>>(
            ahi, alo, whi, wlo, qkv_b + (size_t)i * 3 * D_, nullptr,
            gqkv, nullptr, nullptr, 3 * D_, D_);
        attn_kernel<<<dim3(B_, H_), 256>>>(gqkv, ahi, alo);
        wconv_kernel<<<(D_ * D_) / 1024, 256>>>(out_w + (size_t)i * D_ * D_, whi, wlo);
        mma_gemm<1><<<dim3(4, 512), 256, GEMM_SMEM>>>(
            ahi, alo, whi, wlo, out_b + (size_t)i * D_, gx,
            gx, nullptr, nullptr, D_, D_);
        // --- MLP block ---
        ln_kernel<<<NT, 128>>>(gx, ahi, alo, ln2_g + i * D_, ln2_b + i * D_);
        wconv_kernel<<<(DFF_ * D_) / 1024, 256>>>(w1 + (size_t)i * DFF_ * D_, whi, wlo);
        mma_gemm<2><<<dim3(16, 512), 256, GEMM_SMEM>>>(
            ahi, alo, whi, wlo, b1 + (size_t)i * DFF_, nullptr,
            nullptr, hhi, hlo, DFF_, D_);
        wconv_kernel<<<(D_ * DFF_) / 1024, 256>>>(w2 + (size_t)i * D_ * DFF_, whi, wlo);
        mma_gemm<1><<<dim3(4, 512), 256, GEMM_SMEM>>>(
            hhi, hlo, whi, wlo, b2 + (size_t)i * D_, gx,
            gx, nullptr, nullptr, D_, DFF_);
    }

    pool_kernel<<<(B_ * D_) / 256, 256>>>(gx, gpool);
    hash_kernel<<<B_, 128>>>(gpool, hw, hb, out);
}

// round 16
// speedup vs baseline: 1.9326x; 1.1482x over previous
#include <cuda_runtime.h>
#include <cuda_fp16.h>
#include <cstdint>

// ---------------- problem constants ----------------
#define S_    64
#define B_    1024
#define D_    512
#define H_    8
#define DH_   64
#define NL_   4
#define DFF_  2048
#define NT    (S_ * B_)          // 65536 tokens
#define BD    (B_ * D_)          // 524288
#define KBITS 32

// ---------------- scratch (no cudaMalloc allowed) ----------------
__device__ float g_x[NT * D_];                                   // residual (fp32)
__device__ float g_qkv[NT * 3 * D_];                             // qkv (fp32)
__device__ float g_pool[B_ * D_];
__device__ __half g_ahi[NT * D_];                                // activation hi (fp16)
__device__ __half g_alo[NT * D_];                                // activation lo (fp16)
__device__ __half g_hhi[(size_t)NT * DFF_];                      // mlp hidden hi
__device__ __half g_hlo[(size_t)NT * DFF_];                      // mlp hidden lo
__device__ __half g_whi[DFF_ * D_];                              // weight hi (max 1M)
__device__ __half g_wlo[DFF_ * D_];                              // weight lo

// ---------------- helpers ----------------
__device__ __forceinline__ uint32_t smem_u32(const void* p) {
    uint32_t a;
    asm("{ .reg .u64 t; cvta.to.shared.u64 t, %1; cvt.u32.u64 %0, t; }" : "=r"(a) : "l"(p));
    return a;
}
__device__ __forceinline__ uint32_t packh(float a, float b) {
    const __half ha = __float2half_rn(a), hb = __float2half_rn(b);
    return (uint32_t)__half_as_ushort(ha) | ((uint32_t)__half_as_ushort(hb) << 16);
}
// fp16 split: x = hi + lo, hi/lo both fp16 (11-bit mantissa each)
__device__ __forceinline__ void split2h(float a, float b, uint32_t& hi, uint32_t& lo) {
    const __half ha = __float2half_rn(a), hb = __float2half_rn(b);
    const float ra = a - __half2float(ha);
    const float rb = b - __half2float(hb);
    hi = (uint32_t)__half_as_ushort(ha) | ((uint32_t)__half_as_ushort(hb) << 16);
    lo = packh(ra, rb);
}

#define CP16(dst, src) \
    asm volatile("cp.async.ca.shared.global [%0], [%1], 16;" :: "r"(dst), "l"(src) : "memory")
#define CPCOMMIT() asm volatile("cp.async.commit_group;" ::: "memory")
#define CPWAIT(n)  asm volatile("cp.async.wait_group %0;" :: "n"(n) : "memory")

__device__ __forceinline__ void ldsm4(uint32_t* r, uint32_t addr) {
    asm volatile("ldmatrix.sync.aligned.m8n8.x4.shared.b16 {%0,%1,%2,%3}, [%4];"
                 : "=r"(r[0]), "=r"(r[1]), "=r"(r[2]), "=r"(r[3]) : "r"(addr));
}
__device__ __forceinline__ void mma16816h(float* d, const uint32_t* a, const uint32_t* b) {
    asm volatile("mma.sync.aligned.m16n8k16.row.col.f32.f16.f16.f32 "
                 "{%0,%1,%2,%3}, {%4,%5,%6,%7}, {%8,%9}, {%0,%1,%2,%3};"
                 : "+f"(d[0]), "+f"(d[1]), "+f"(d[2]), "+f"(d[3])
                 : "r"(a[0]), "r"(a[1]), "r"(a[2]), "r"(a[3]), "r"(b[0]), "r"(b[1]));
}

__device__ __forceinline__ float qgelu(float t) { return t / (1.0f + __expf(-1.702f * t)); }

// smem: 2 stages x 4 arrays x (128 rows x 128B) = 128KB
#define STG_SZ   65536
#define OFF_ALO  16384
#define OFF_WHI  32768
#define OFF_WLO  49152
#define GEMM_SMEM (2 * STG_SZ)

// ---------------- MMA GEMM: C[n,m] = epi(sum_k A[n,k]*W[m,k] + bias[m]) ----------------
// CTA tile: 128 tokens x 128 outputs, KC=64, 8 warps (warp tile 64 tok x 32 out).
// fp16 split arithmetic. NPASS=3: Ahi*Whi + Alo*Whi + Ahi*Wlo (residual writers).
// NPASS=2: Ahi*Whi + Alo*Whi (drops ~2^-12 term; Wlo never loaded).
// EPI: 0 = f32 +bias ; 1 = f32 +bias+res ; 2 = QuickGELU -> fp16 hi/lo outputs
template <int EPI, int NPASS>
__global__ __launch_bounds__(256, 1) void mma_gemm(
    const __half* __restrict__ Ahi, const __half* __restrict__ Alo,
    const __half* __restrict__ Whi, const __half* __restrict__ Wlo,
    const float* __restrict__ bias, const float* __restrict__ res,
    float* __restrict__ C, __half* __restrict__ Chi, __half* __restrict__ Clo,
    int M, int K)
{
    extern __shared__ __align__(128) char smem[];
    const uint32_t sb = smem_u32(smem);
    const int tid = threadIdx.x;
    const int lane = tid & 31;
    const int wid = tid >> 5;
    const int m0 = blockIdx.x * 128;
    const int n0 = blockIdx.y * 128;
    const int wm = (wid & 1) * 64;
    const int wn = (wid >> 1) * 32;
    const int NCH = K >> 6;
    const int lcc = tid & 7;

    float acc[4][4][4];
    #pragma unroll
    for (int a = 0; a < 4; a++)
        #pragma unroll
        for (int b = 0; b < 4; b++)
            #pragma unroll
            for (int c = 0; c < 4; c++) acc[a][b][c] = 0.0f;

    auto load_stage = [&](int c, int s) {
        const uint32_t stb = sb + s * STG_SZ;
        #pragma unroll
        for (int j = 0; j < 4; j++) {
            const int r = (j * 256 + tid) >> 3;
            const uint32_t dst = (uint32_t)(r * 128 + ((lcc ^ (r & 7)) << 4));
            const size_t aoff = (size_t)(n0 + r) * K + c * 64 + lcc * 8;
            const size_t woff = (size_t)(m0 + r) * K + c * 64 + lcc * 8;
            CP16(stb + dst,           Ahi + aoff);
            CP16(stb + OFF_ALO + dst, Alo + aoff);
            CP16(stb + OFF_WHI + dst, Whi + woff);
            if (NPASS == 3) CP16(stb + OFF_WLO + dst, Wlo + woff);
        }
        CPCOMMIT();
    };

    load_stage(0, 0);

    const int g  = lane >> 3;
    const int lr = lane & 7;

    for (int c = 0; c < NCH; c++) {
        if (c + 1 < NCH) { load_stage(c + 1, (c + 1) & 1); CPWAIT(1); }
        else             { CPWAIT(0); }
        __syncthreads();

        const uint32_t stb = sb + (c & 1) * STG_SZ;
        #pragma unroll
        for (int ks = 0; ks < 4; ks++) {
            uint32_t af[4][4], alf[4][4], bf[2][4], blf[2][4];
            #pragma unroll
            for (int mi = 0; mi < 4; mi++) {
                const int row = wm + mi * 16 + ((g & 1) << 3) + lr;
                const int ch = ks * 2 + (g >> 1);
                const uint32_t ad = stb + row * 128 + ((ch ^ (row & 7)) << 4);
                ldsm4(af[mi], ad);
                ldsm4(alf[mi], ad + OFF_ALO);
            }
            #pragma unroll
            for (int np = 0; np < 2; np++) {
                const int row = wn + np * 16 + ((g >> 1) << 3) + lr;
                const int ch = ks * 2 + (g & 1);
                const uint32_t bd = stb + OFF_WHI + row * 128 + ((ch ^ (row & 7)) << 4);
                ldsm4(bf[np], bd);
                if (NPASS == 3) ldsm4(blf[np], bd + 16384);
            }
            // pass 1: Ahi*Whi
            #pragma unroll
            for (int mi = 0; mi < 4; mi++)
                #pragma unroll
                for (int nt = 0; nt < 4; nt++)
                    mma16816h(acc[mi][nt], af[mi], &bf[nt >> 1][(nt & 1) * 2]);
            // pass 2: Alo*Whi
            #pragma unroll
            for (int mi = 0; mi < 4; mi++)
                #pragma unroll
                for (int nt = 0; nt < 4; nt++)
                    mma16816h(acc[mi][nt], alf[mi], &bf[nt >> 1][(nt & 1) * 2]);
            // pass 3: Ahi*Wlo (residual writers only)
            if (NPASS == 3) {
                #pragma unroll
                for (int mi = 0; mi < 4; mi++)
                    #pragma unroll
                    for (int nt = 0; nt < 4; nt++)
                        mma16816h(acc[mi][nt], af[mi], &blf[nt >> 1][(nt & 1) * 2]);
            }
        }
        __syncthreads();
    }

    const int r4 = lane >> 2;
    const int c2 = (lane & 3) * 2;
    #pragma unroll
    for (int mi = 0; mi < 4; mi++) {
        #pragma unroll
        for (int nt = 0; nt < 4; nt++) {
            const int row = n0 + wm + mi * 16 + r4;
            const int col = m0 + wn + nt * 8 + c2;
            const float b0 = bias[col], b1 = bias[col + 1];
            float v0 = acc[mi][nt][0] + b0, v1 = acc[mi][nt][1] + b1;
            float v2 = acc[mi][nt][2] + b0, v3 = acc[mi][nt][3] + b1;
            const size_t o0 = (size_t)row * M + col;
            const size_t o1 = (size_t)(row + 8) * M + col;
            if (EPI == 1) {
                const float2 r0 = *(const float2*)&res[o0];
                const float2 r1 = *(const float2*)&res[o1];
                v0 += r0.x; v1 += r0.y; v2 += r1.x; v3 += r1.y;
            }
            if (EPI == 2) {
                v0 = qgelu(v0); v1 = qgelu(v1); v2 = qgelu(v2); v3 = qgelu(v3);
                uint32_t h0, l0, h1, l1;
                split2h(v0, v1, h0, l0);
                split2h(v2, v3, h1, l1);
                *(uint32_t*)&Chi[o0] = h0; *(uint32_t*)&Clo[o0] = l0;
                *(uint32_t*)&Chi[o1] = h1; *(uint32_t*)&Clo[o1] = l1;
            } else {
                *(float2*)&C[o0] = make_float2(v0, v1);
                *(float2*)&C[o1] = make_float2(v2, v3);
            }
        }
    }
}

// ---------------- weight convert: fp32 -> fp16 hi/lo ----------------
__global__ void wconv_kernel(const float* __restrict__ w,
                             __half* __restrict__ hi,
                             __half* __restrict__ lo) {
    const int i = blockIdx.x * blockDim.x + threadIdx.x;
    const float4 v = *(const float4*)&w[i * 4];
    uint32_t h0, l0, h1, l1;
    split2h(v.x, v.y, h0, l0);
    split2h(v.z, v.w, h1, l1);
    *(uint2*)&hi[i * 4] = make_uint2(h0, h1);
    *(uint2*)&lo[i * 4] = make_uint2(l0, l1);
}

// ---------------- positional encoding add ----------------
__global__ void pe_add_kernel(const float* __restrict__ xin, float* __restrict__ xout) {
    int idx = blockIdx.x * blockDim.x + threadIdx.x;
    int d = idx & (D_ - 1);
    int s = idx >> 19;
    int j2 = d & ~1;
    float ang = (float)s * expf((float)j2 * (-9.210340371976184f / 512.0f));
    float pe = ((d & 1) ? cosf(ang) : sinf(ang)) * 0.04419417382415922f;
    xout[idx] = xin[idx] + pe;
}

// ---------------- layernorm -> fp16 hi/lo ----------------
__global__ void ln_kernel(const float* __restrict__ x,
                          __half* __restrict__ yhi, __half* __restrict__ ylo,
                          const float* __restrict__ g, const float* __restrict__ b) {
    const int row = blockIdx.x;
    const int t = threadIdx.x;
    const size_t base = (size_t)row * D_ + t * 4;
    const float4 v = *(const float4*)&x[base];
    float s = v.x + v.y + v.z + v.w;
    float q = v.x * v.x + v.y * v.y + v.z * v.z + v.w * v.w;
    #pragma unroll
    for (int m = 16; m > 0; m >>= 1) {
        s += __shfl_xor_sync(0xffffffffu, s, m);
        q += __shfl_xor_sync(0xffffffffu, q, m);
    }
    __shared__ float ss[4], qq[4];
    if ((t & 31) == 0) { ss[t >> 5] = s; qq[t >> 5] = q; }
    __syncthreads();
    s = ss[0] + ss[1] + ss[2] + ss[3];
    q = qq[0] + qq[1] + qq[2] + qq[3];
    const float mean = s * (1.0f / 512.0f);
    const float var  = q * (1.0f / 512.0f) - mean * mean;
    const float rstd = rsqrtf(var + 1e-5f);
    const float4 gg = *(const float4*)&g[t * 4];
    const float4 bb = *(const float4*)&b[t * 4];
    const float o0 = (v.x - mean) * rstd * gg.x + bb.x;
    const float o1 = (v.y - mean) * rstd * gg.y + bb.y;
    const float o2 = (v.z - mean) * rstd * gg.z + bb.z;
    const float o3 = (v.w - mean) * rstd * gg.w + bb.w;
    uint32_t h0, l0, h1, l1;
    split2h(o0, o1, h0, l0);
    split2h(o2, o3, h1, l1);
    *(uint2*)&yhi[base] = make_uint2(h0, h1);
    *(uint2*)&ylo[base] = make_uint2(l0, l1);
}

// ---------------- attention: one CTA per (batch, head); fp16 hi/lo output ----------------
// kst XOR swizzle: element (d, t) lives at kst[d*64 + (t ^ (4*(d>>2)))].
__global__ __launch_bounds__(256) void attn_kernel(const float* __restrict__ qkv,
                                                   __half* __restrict__ ohi,
                                                   __half* __restrict__ olo) {
    __shared__ __align__(16) float qs[64 * 64];
    __shared__ __align__(16) float kst[64 * 64];
    __shared__ __align__(16) float vs[64 * 64];

    const int b = blockIdx.x;
    const int h = blockIdx.y;
    const int tid = threadIdx.x;
    const float* base = qkv + (size_t)b * (3 * D_) + h * DH_;

    #pragma unroll
    for (int it = 0; it < 4; it++) {
        const int idx = tid + it * 256;
        const int s = idx >> 4;
        const int f = idx & 15;
        const size_t g = (size_t)s * (B_ * 3 * D_) + f * 4;
        const float4 qv = *(const float4*)(base + g);
        const float4 kv = *(const float4*)(base + 512 + g);
        const float4 vv = *(const float4*)(base + 1024 + g);
        *(float4*)&qs[s * 64 + f * 4] = qv;
        const int swc = s ^ (f * 4);
        kst[(f * 4 + 0) * 64 + swc] = kv.x;
        kst[(f * 4 + 1) * 64 + swc] = kv.y;
        kst[(f * 4 + 2) * 64 + swc] = kv.z;
        kst[(f * 4 + 3) * 64 + swc] = kv.w;
        *(float4*)&vs[s * 64 + f * 4] = vv;
    }
    __syncthreads();

    const int tx = tid & 15;
    const int ty = tid >> 4;

    float sc[4][4] = {};
    #pragma unroll 4
    for (int d0 = 0; d0 < 64; d0 += 4) {
        const int txx = (tx ^ (d0 >> 2)) * 4;
        const float4 k0 = *(const float4*)&kst[(d0 + 0) * 64 + txx];
        const float4 k1 = *(const float4*)&kst[(d0 + 1) * 64 + txx];
        const float4 k2 = *(const float4*)&kst[(d0 + 2) * 64 + txx];
        const float4 k3 = *(const float4*)&kst[(d0 + 3) * 64 + txx];
        #pragma unroll
        for (int i = 0; i < 4; i++) {
            const float4 q = *(const float4*)&qs[(ty * 4 + i) * 64 + d0];
            sc[i][0] += q.x * k0.x + q.y * k1.x + q.z * k2.x + q.w * k3.x;
            sc[i][1] += q.x * k0.y + q.y * k1.y + q.z * k2.y + q.w * k3.y;
            sc[i][2] += q.x * k0.z + q.y * k1.z + q.z * k2.z + q.w * k3.z;
            sc[i][3] += q.x * k0.w + q.y * k1.w + q.z * k2.w + q.w * k3.w;
        }
    }

    float p[4][4];
    #pragma unroll
    for (int i = 0; i < 4; i++) {
        #pragma unroll
        for (int j = 0; j < 4; j++) sc[i][j] *= 0.125f;
        float m = fmaxf(fmaxf(sc[i][0], sc[i][1]), fmaxf(sc[i][2], sc[i][3]));
        #pragma unroll
        for (int msk = 1; msk < 16; msk <<= 1) m = fmaxf(m, __shfl_xor_sync(0xffffffffu, m, msk));
        float s = 0.0f;
        #pragma unroll
        for (int j = 0; j < 4; j++) { p[i][j] = __expf(sc[i][j] - m); s += p[i][j]; }
        #pragma unroll
        for (int msk = 1; msk < 16; msk <<= 1) s += __shfl_xor_sync(0xffffffffu, s, msk);
        const float inv = 1.0f / s;
        #pragma unroll
        for (int j = 0; j < 4; j++) p[i][j] *= inv;
    }

    __syncthreads();
    #pragma unroll
    for (int i = 0; i < 4; i++)
        *(float4*)&qs[(ty * 4 + i) * 64 + tx * 4] =
            make_float4(p[i][0], p[i][1], p[i][2], p[i][3]);
    __syncthreads();

    float oc[4][4] = {};
    #pragma unroll 4
    for (int t = 0; t < 64; t++) {
        const float4 vv = *(const float4*)&vs[t * 64 + tx * 4];
        #pragma unroll
        for (int i = 0; i < 4; i++) {
            const float pp = qs[(ty * 4 + i) * 64 + t];
            oc[i][0] += pp * vv.x; oc[i][1] += pp * vv.y;
            oc[i][2] += pp * vv.z; oc[i][3] += pp * vv.w;
        }
    }
    #pragma unroll
    for (int i = 0; i < 4; i++) {
        const int s = ty * 4 + i;
        const size_t off = (size_t)(s * B_ + b) * D_ + h * DH_ + tx * 4;
        uint32_t h0, l0, h1, l1;
        split2h(oc[i][0], oc[i][1], h0, l0);
        split2h(oc[i][2], oc[i][3], h1, l1);
        *(uint2*)&ohi[off] = make_uint2(h0, h1);
        *(uint2*)&olo[off] = make_uint2(l0, l1);
    }
}

// ---------------- mean over S ----------------
__global__ void pool_kernel(const float* __restrict__ x, float* __restrict__ pooled) {
    const int idx = blockIdx.x * blockDim.x + threadIdx.x;
    float s = 0.0f;
    #pragma unroll
    for (int t = 0; t < S_; t++) s += x[(size_t)t * BD + idx];
    pooled[idx] = s * (1.0f / 64.0f);
}

// ---------------- hashing head ----------------
__global__ void hash_kernel(const float* __restrict__ pooled, const float* __restrict__ hw,
                            const float* __restrict__ hb, float* __restrict__ out) {
    const int b = blockIdx.x;
    const int t = threadIdx.x;
    __shared__ float row[512];
    __shared__ float part[128];
    *(float4*)&row[t * 4] = *(const float4*)&pooled[(size_t)b * D_ + t * 4];
    __syncthreads();
    const int k = t & 31;
    const int pi = t >> 5;
    const float* w = hw + (size_t)k * D_ + pi * 128;
    const float* r = row + pi * 128;
    float s = 0.0f;
    #pragma unroll 8
    for (int d = 0; d < 128; d++) s += r[d] * w[d];
    part[t] = s;
    __syncthreads();
    if (t < 32) {
        const float v = part[t] + part[t + 32] + part[t + 64] + part[t + 96] + hb[t];
        out[(size_t)b * KBITS + t] = tanhf(v);
    }
}

// ---------------- orchestration ----------------
extern "C" void kernel_launch(void* const* d_in, const int* in_sizes, int n_in,
                              void* d_out, int out_size) {
    const float* x_in  = (const float*)d_in[0];
    const float* ln1_g = (const float*)d_in[1];
    const float* ln1_b = (const float*)d_in[2];
    const float* qkv_w = (const float*)d_in[3];
    const float* qkv_b = (const float*)d_in[4];
    const float* out_w = (const float*)d_in[5];
    const float* out_b = (const float*)d_in[6];
    const float* ln2_g = (const float*)d_in[7];
    const float* ln2_b = (const float*)d_in[8];
    const float* w1    = (const float*)d_in[9];
    const float* b1    = (const float*)d_in[10];
    const float* w2    = (const float*)d_in[11];
    const float* b2    = (const float*)d_in[12];
    const float* hw    = (const float*)d_in[13];
    const float* hb    = (const float*)d_in[14];
    float* out = (float*)d_out;

    float *gx, *gqkv, *gpool;
    __half *ahi, *alo, *hhi, *hlo, *whi, *wlo;
    cudaGetSymbolAddress((void**)&gx,    g_x);
    cudaGetSymbolAddress((void**)&gqkv,  g_qkv);
    cudaGetSymbolAddress((void**)&gpool, g_pool);
    cudaGetSymbolAddress((void**)&ahi,   g_ahi);
    cudaGetSymbolAddress((void**)&alo,   g_alo);
    cudaGetSymbolAddress((void**)&hhi,   g_hhi);
    cudaGetSymbolAddress((void**)&hlo,   g_hlo);
    cudaGetSymbolAddress((void**)&whi,   g_whi);
    cudaGetSymbolAddress((void**)&wlo,   g_wlo);

    cudaFuncSetAttribute(mma_gemm<0,2>, cudaFuncAttributeMaxDynamicSharedMemorySize, GEMM_SMEM);
    cudaFuncSetAttribute(mma_gemm<1,3>, cudaFuncAttributeMaxDynamicSharedMemorySize, GEMM_SMEM);
    cudaFuncSetAttribute(mma_gemm<2,2>, cudaFuncAttributeMaxDynamicSharedMemorySize, GEMM_SMEM);

    pe_add_kernel<<<(NT * D_) / 256, 256>>>(x_in, gx);

    for (int i = 0; i < NL_; i++) {
        // --- attention block ---
        ln_kernel<<<NT, 128>>>(gx, ahi, alo, ln1_g + i * D_, ln1_b + i * D_);
        wconv_kernel<<<(3 * D_ * D_) / 1024, 256>>>(qkv_w + (size_t)i * 3 * D_ * D_, whi, wlo);
        mma_gemm<0,2><<<dim3(12, 512), 256, GEMM_SMEM>>>(
            ahi, alo, whi, wlo, qkv_b + (size_t)i * 3 * D_, nullptr,
            gqkv, nullptr, nullptr, 3 * D_, D_);
        attn_kernel<<<dim3(B_, H_), 256>>>(gqkv, ahi, alo);
        wconv_kernel<<<(D_ * D_) / 1024, 256>>>(out_w + (size_t)i * D_ * D_, whi, wlo);
        mma_gemm<1,3><<<dim3(4, 512), 256, GEMM_SMEM>>>(
            ahi, alo, whi, wlo, out_b + (size_t)i * D_, gx,
            gx, nullptr, nullptr, D_, D_);
        // --- MLP block ---
        ln_kernel<<<NT, 128>>>(gx, ahi, alo, ln2_g + i * D_, ln2_b + i * D_);
        wconv_kernel<<<(DFF_ * D_) / 1024, 256>>>(w1 + (size_t)i * DFF_ * D_, whi, wlo);
        mma_gemm<2,2><<<dim3(16, 512), 256, GEMM_SMEM>>>(
            ahi, alo, whi, wlo, b1 + (size_t)i * DFF_, nullptr,
            nullptr, hhi, hlo, DFF_, D_);
        wconv_kernel<<<(D_ * DFF_) / 1024, 256>>>(w2 + (size_t)i * D_ * DFF_, whi, wlo);
        mma_gemm<1,3><<<dim3(4, 512), 256, GEMM_SMEM>>>(
            hhi, hlo, whi, wlo, b2 + (size_t)i * D_, gx,
            gx, nullptr, nullptr, D_, DFF_);
    }

    pool_kernel<<<(B_ * D_) / 256, 256>>>(gx, gpool);
    hash_kernel<<<B_, 128>>>(gpool, hw, hb, out);
}